// round 2
// baseline (speedup 1.0000x reference)
#include <cuda_runtime.h>

// ConvSquare: out = conv3x3(x * f(alpha), w) + bias,  f(t) = (a*t + b)*t + c
// B=4, C=64, O=64, H=W=128, K=3, pad=1.
//
// Key identity: the "spatially varying kernel" from unfolded alpha depends only
// on the SOURCE pixel (m+k-1, n+l-1), so the whole op is a standard 3x3 conv
// on the premultiplied input y = x * f(alpha). We fuse the premultiply into
// the shared-memory tile load.

#define BATCH 4
#define CHN   64
#define OCH   64
#define HH    128
#define WW    128

#define TH 32          // output tile height
#define TW 32          // output tile width
#define CC 8           // input-channel chunk held in smem
#define OG 16          // output channels per CTA
#define HALO 34        // TH+2
#define XPITCH 36      // smem row pitch (even -> aligned float2, no conflicts)

#define W_S_FLOATS (OG * CHN * 9)          // 9216
#define FK_FLOATS  (HALO * XPITCH)         // 1224
#define XS_FLOATS  (CC * HALO * XPITCH)    // 9792
#define SMEM_FLOATS (W_S_FLOATS + FK_FLOATS + XS_FLOATS)
#define SMEM_BYTES  (SMEM_FLOATS * 4)      // 80928 bytes

__global__ __launch_bounds__(256, 2)
void conv_sq_kernel(const float* __restrict__ x,
                    const float* __restrict__ alpha,
                    const float* __restrict__ wgt,
                    const float* __restrict__ bias,
                    const float* __restrict__ pa,
                    const float* __restrict__ pb,
                    const float* __restrict__ pc,
                    float* __restrict__ out)
{
    extern __shared__ float smem[];
    float* w_s  = smem;                         // [OG][CHN][9], contiguous slice of global W
    float* fk_s = w_s + W_S_FLOATS;             // [HALO][XPITCH]  f(alpha) halo tile
    float* x_s  = fk_s + FK_FLOATS;             // [CC][HALO][XPITCH] premultiplied input

    const int tid = threadIdx.x;
    const int bz  = blockIdx.z;
    const int b   = bz >> 2;        // batch
    const int og  = bz & 3;         // output-channel group (16 each)
    const int gy0 = blockIdx.y * TH;
    const int gx0 = blockIdx.x * TW;
    const int y0  = gy0 - 1;        // halo origin
    const int x0  = gx0 - 1;

    // ---- load weight slice [og*16 .. og*16+15][64][3][3] : contiguous 9216 floats
    {
        const float* wg = wgt + og * OG * CHN * 9;
        #pragma unroll 1
        for (int i = tid; i < W_S_FLOATS; i += 256) w_s[i] = wg[i];
    }

    // ---- load alpha halo tile, compute f(alpha) once (reused by all 64 channels)
    {
        const float A = pa[0], Bq = pb[0], Cq = pc[0];
        const float* ap = alpha + b * HH * WW;
        #pragma unroll 1
        for (int i = tid; i < HALO * HALO; i += 256) {
            int r  = i / HALO;
            int cl = i - r * HALO;
            int gy = y0 + r, gx = x0 + cl;
            float v = 0.0f;
            if (gy >= 0 && gy < HH && gx >= 0 && gx < WW) {
                float t = __ldg(ap + gy * WW + gx);
                v = (A * t + Bq) * t + Cq;
            }
            fk_s[r * XPITCH + cl] = v;
        }
    }

    // thread -> 2x2 pixel block
    const int ty  = tid >> 4;
    const int tx  = tid & 15;
    const int py0 = 2 * ty;     // tile-local row of pixel block
    const int px0 = 2 * tx;     // tile-local col (even -> float2 aligned)

    float acc[OG * 4];
    #pragma unroll
    for (int i = 0; i < OG * 4; i++) acc[i] = 0.0f;

    #pragma unroll 1
    for (int cc0 = 0; cc0 < CHN; cc0 += CC) {
        __syncthreads();   // protect x_s reuse from previous chunk's readers

        // ---- load CC premultiplied input channels into smem
        #pragma unroll 1
        for (int ci = 0; ci < CC; ci++) {
            const float* xp = x + ((b * CHN + cc0 + ci) * HH) * WW;
            float* xd = x_s + ci * HALO * XPITCH;
            #pragma unroll 1
            for (int i = tid; i < HALO * HALO; i += 256) {
                int r  = i / HALO;
                int cl = i - r * HALO;
                int gy = y0 + r, gx = x0 + cl;
                float v = 0.0f;
                if (gy >= 0 && gy < HH && gx >= 0 && gx < WW)
                    v = __ldg(xp + gy * WW + gx);
                xd[r * XPITCH + cl] = v * fk_s[r * XPITCH + cl];
            }
        }
        __syncthreads();

        // ---- compute: 16 o-channels x 2x2 pixels per thread
        #pragma unroll 1
        for (int ci = 0; ci < CC; ci++) {
            const float* xb = x_s + ci * HALO * XPITCH + py0 * XPITCH + px0;
            float xw[4][4];
            #pragma unroll
            for (int r = 0; r < 4; r++) {
                float2 u0 = *(const float2*)(xb + r * XPITCH);
                float2 u1 = *(const float2*)(xb + r * XPITCH + 2);
                xw[r][0] = u0.x; xw[r][1] = u0.y;
                xw[r][2] = u1.x; xw[r][3] = u1.y;
            }
            const float* wp = w_s + (cc0 + ci) * 9;
            #pragma unroll
            for (int o = 0; o < OG; o++) {
                const float* wo = wp + o * (CHN * 9);
                #pragma unroll
                for (int k = 0; k < 3; k++) {
                    #pragma unroll
                    for (int l = 0; l < 3; l++) {
                        float wv = wo[k * 3 + l];
                        acc[o*4+0] = fmaf(wv, xw[k  ][l  ], acc[o*4+0]);
                        acc[o*4+1] = fmaf(wv, xw[k  ][l+1], acc[o*4+1]);
                        acc[o*4+2] = fmaf(wv, xw[k+1][l  ], acc[o*4+2]);
                        acc[o*4+3] = fmaf(wv, xw[k+1][l+1], acc[o*4+3]);
                    }
                }
            }
        }
    }

    // ---- epilogue: add bias, vectorized stores
    const int gy = gy0 + py0;
    const int gx = gx0 + px0;
    #pragma unroll
    for (int o = 0; o < OG; o++) {
        float bo = __ldg(bias + og * OG + o);
        float* op = out + (((b * OCH) + og * OG + o) * HH + gy) * WW + gx;
        float2 s0 = make_float2(acc[o*4+0] + bo, acc[o*4+1] + bo);
        float2 s1 = make_float2(acc[o*4+2] + bo, acc[o*4+3] + bo);
        *(float2*)(op)      = s0;
        *(float2*)(op + WW) = s1;
    }
}

extern "C" void kernel_launch(void* const* d_in, const int* in_sizes, int n_in,
                              void* d_out, int out_size)
{
    const float* x     = (const float*)d_in[0];
    const float* alpha = (const float*)d_in[1];
    const float* wgt   = (const float*)d_in[2];
    const float* bias  = (const float*)d_in[3];
    const float* pa    = (const float*)d_in[4];
    const float* pb    = (const float*)d_in[5];
    const float* pc    = (const float*)d_in[6];
    float* out = (float*)d_out;

    cudaFuncSetAttribute(conv_sq_kernel,
                         cudaFuncAttributeMaxDynamicSharedMemorySize, SMEM_BYTES);

    dim3 grid(WW / TW, HH / TH, BATCH * (OCH / OG));  // 4 x 4 x 16
    dim3 block(256);
    conv_sq_kernel<<<grid, block, SMEM_BYTES>>>(x, alpha, wgt, bias, pa, pb, pc, out);
}